// round 2
// baseline (speedup 1.0000x reference)
#include <cuda_runtime.h>
#include <cstdint>

// ---------------------------------------------------------------------------
// DFine Multiscale Deformable Attention
//   B=16, Q=300, HIDDEN=256, N_HEADS=8, d=32
//   SPATIAL = (100,100),(50,50),(25,25),(13,13)  -> S=13294
//   NUM_POINTS = 4 per level -> p_total=16, total_points = 128
//   W_off: (256, 256), W_attn: (256, 128)
// Output = concat( out[B,Q,256], aw[B,Q,8,16] )  (float32)
// ---------------------------------------------------------------------------

#define NB        16
#define NQ        300
#define NBQ       (NB * NQ)          // 4800
#define HIDDEN    256
#define NHEADS    8
#define DHEAD     32
#define PTOT      16                 // points per head
#define NOUT0     (NBQ * HIDDEN)     // 1228800 floats (out)
#define NOUT1     (NBQ * NHEADS * PTOT) // 614400 floats (aw)
#define SENC      13294

// per-(b,q): 8 heads * 16 points * 2 coords
__device__ float g_loc[NBQ * NHEADS * PTOT * 2];   // ~4.9 MB scratch

// ---------------------------------------------------------------------------
// Kernel A: projection GEMM (offsets + attn logits), softmax, sampling
// locations. One block handles G=16 consecutive (b,q) rows with a register
// tile; 384 threads = one output column each (256 offset cols + 128 attn).
// ---------------------------------------------------------------------------
#define GTILE 16

__global__ __launch_bounds__(384)
void dfine_proj_kernel(const float* __restrict__ hs,        // (BQ, 256)
                       const float* __restrict__ ref,       // (BQ, 4)
                       const float* __restrict__ W_off,     // (256, 256)
                       const float* __restrict__ b_off,     // (256,)
                       const float* __restrict__ W_attn,    // (256, 128)
                       const float* __restrict__ b_attn,    // (128,)
                       float* __restrict__ out_aw)          // d_out + NOUT0
{
    __shared__ float sh[GTILE * HIDDEN];      // 16 KB
    const int bq0 = blockIdx.x * GTILE;
    const int tid = threadIdx.x;              // 0..383

    // cooperative load of 16 hidden rows
    for (int i = tid; i < GTILE * HIDDEN; i += 384)
        sh[i] = hs[(size_t)bq0 * HIDDEN + i];
    __syncthreads();

    const bool is_off = (tid < 256);
    const float* Wp = is_off ? (W_off + tid) : (W_attn + (tid - 256));
    const int    ws = is_off ? 256 : 128;
    const float  bias = is_off ? b_off[tid] : b_attn[tid - 256];

    float acc[GTILE];
#pragma unroll
    for (int g = 0; g < GTILE; ++g) acc[g] = bias;

#pragma unroll 4
    for (int k = 0; k < HIDDEN; ++k) {
        const float wv = __ldg(Wp + (size_t)k * ws);
#pragma unroll
        for (int g = 0; g < GTILE; ++g)
            acc[g] = fmaf(sh[g * HIDDEN + k], wv, acc[g]);
    }

    if (!is_off) {
        // ---- softmax over the 16 points of each head (16-lane groups) ----
        const int idx = tid - 256;            // h*16 + p
#pragma unroll
        for (int g = 0; g < GTILE; ++g) {
            float v = acc[g];
            float m = v;
#pragma unroll
            for (int o = 8; o; o >>= 1)
                m = fmaxf(m, __shfl_xor_sync(0xffffffffu, m, o));
            float e = __expf(v - m);
            float s = e;
#pragma unroll
            for (int o = 8; o; o >>= 1)
                s += __shfl_xor_sync(0xffffffffu, s, o);
            out_aw[(size_t)(bq0 + g) * (NHEADS * PTOT) + idx] = e / s;
        }
    } else {
        // ---- sampling locations:
        // off index tid = ((h*16+p)*2 + c); loc = ref_xy + off*0.25*ref_wh*0.5
        const int c = tid & 1;
#pragma unroll
        for (int g = 0; g < GTILE; ++g) {
            const float4 r = __ldg((const float4*)ref + (bq0 + g));
            const float base = c ? r.y : r.x;
            const float wh   = c ? r.w : r.z;
            g_loc[(size_t)(bq0 + g) * 256 + tid] = fmaf(acc[g] * 0.125f, wh, base);
        }
    }
}

// ---------------------------------------------------------------------------
// Kernel B: bilinear sampling + attention-weighted sum.
// One block per (b,q): 8 warps = 8 heads; lane = channel d (0..31).
// Every tap load is one coalesced 128B line.
// ---------------------------------------------------------------------------
__global__ __launch_bounds__(256)
void dfine_sample_kernel(const float* __restrict__ enc,     // (B, S, 256)
                         const float* __restrict__ aw,      // (BQ, 128)
                         float* __restrict__ out)           // (BQ, 256)
{
    __shared__ float s_loc[256];
    __shared__ float s_aw[128];

    const int bq = blockIdx.x;
    const int b  = bq / NQ;
    const int h  = threadIdx.x >> 5;
    const int d  = threadIdx.x & 31;

    s_loc[threadIdx.x] = g_loc[(size_t)bq * 256 + threadIdx.x];
    if (threadIdx.x < 128)
        s_aw[threadIdx.x] = aw[(size_t)bq * 128 + threadIdx.x];
    __syncthreads();

    const float* encb = enc + (size_t)b * SENC * 256;

    // level constants (4 points per level)
    const int   lw[4]    = {100, 50, 25, 13};
    const int   lh[4]    = {100, 50, 25, 13};
    const int   lstart[4]= {0, 10000, 12500, 13125};

    float acc = 0.0f;

#pragma unroll
    for (int p = 0; p < PTOT; ++p) {
        const int lvl = p >> 2;
        const int w   = lw[lvl];
        const int hh  = lh[lvl];
        const int st  = lstart[lvl];

        const float lx = s_loc[(h * PTOT + p) * 2 + 0];
        const float ly = s_loc[(h * PTOT + p) * 2 + 1];
        const float a  = s_aw[h * PTOT + p];

        const float x = lx * (float)w  - 0.5f;
        const float y = ly * (float)hh - 0.5f;
        const float x0f = floorf(x);
        const float y0f = floorf(y);
        const int   x0  = (int)x0f;
        const int   y0  = (int)y0f;
        const float wx1 = x - x0f, wx0 = 1.0f - wx1;
        const float wy1 = y - y0f, wy0 = 1.0f - wy1;

        const bool vx0 = (x0 >= 0)     && (x0 < w);
        const bool vx1 = (x0 + 1 >= 0) && (x0 + 1 < w);
        const bool vy0 = (y0 >= 0)     && (y0 < hh);
        const bool vy1 = (y0 + 1 >= 0) && (y0 + 1 < hh);

        // base index helper: ((st + yi*w + xi)*8 + h)*32 + d
        const size_t rowbase = ((size_t)st) * 256 + (size_t)h * 32 + d;

        float v00 = 0.f, v01 = 0.f, v10 = 0.f, v11 = 0.f;
        if (vy0 && vx0) v00 = __ldg(encb + rowbase + ((size_t)y0 * w + x0) * 256);
        if (vy0 && vx1) v01 = __ldg(encb + rowbase + ((size_t)y0 * w + x0 + 1) * 256);
        if (vy1 && vx0) v10 = __ldg(encb + rowbase + ((size_t)(y0 + 1) * w + x0) * 256);
        if (vy1 && vx1) v11 = __ldg(encb + rowbase + ((size_t)(y0 + 1) * w + x0 + 1) * 256);

        float s = v00 * (wy0 * wx0) + v01 * (wy0 * wx1)
                + v10 * (wy1 * wx0) + v11 * (wy1 * wx1);
        acc = fmaf(a, s, acc);
    }

    out[(size_t)bq * 256 + h * 32 + d] = acc;
}

// ---------------------------------------------------------------------------
extern "C" void kernel_launch(void* const* d_in, const int* in_sizes, int n_in,
                              void* d_out, int out_size)
{
    const float* hs     = (const float*)d_in[0];   // (B,Q,256)
    const float* enc    = (const float*)d_in[1];   // (B,S,256)
    const float* ref    = (const float*)d_in[2];   // (B,Q,1,4)
    const float* W_off  = (const float*)d_in[3];   // (256,256)
    const float* b_off  = (const float*)d_in[4];   // (256,)
    const float* W_attn = (const float*)d_in[5];   // (256,128)
    const float* b_attn = (const float*)d_in[6];   // (128,)

    float* out    = (float*)d_out;                 // (B,Q,256)
    float* out_aw = (float*)d_out + NOUT0;         // (B,Q,8,16)

    dfine_proj_kernel<<<NBQ / GTILE, 384>>>(hs, ref, W_off, b_off, W_attn,
                                            b_attn, out_aw);
    dfine_sample_kernel<<<NBQ, 256>>>(enc, out_aw, out);
}

// round 3
// speedup vs baseline: 2.0446x; 2.0446x over previous
#include <cuda_runtime.h>
#include <cstdint>

// ---------------------------------------------------------------------------
// DFine Multiscale Deformable Attention
//   B=16, Q=300, HIDDEN=256, N_HEADS=8, d=32
//   SPATIAL = (100,100),(50,50),(25,25),(13,13)  -> S=13294
//   NUM_POINTS = 4 per level -> p_total=16, total_points = 128
// Output = concat( out[B,Q,256], aw[B,Q,8,16] )  (float32)
// ---------------------------------------------------------------------------

#define NB        16
#define NQ        300
#define NBQ       (NB * NQ)          // 4800
#define HIDDEN    256
#define NHEADS    8
#define PTOT      16
#define NOUT0     (NBQ * HIDDEN)
#define SENC      13294

// per-(b,q): 8 heads * 16 points * 2 coords
__device__ float g_loc[NBQ * NHEADS * PTOT * 2];

// ---------------------------------------------------------------------------
// Kernel A: projection GEMM (offsets + attn logits) + softmax + sampling locs.
// 384 threads = one output column each (256 offset + 128 attn), GTILE=16 rows
// in registers. Software-pipelined W prefetch (8-deep) + float4 shared loads.
// ---------------------------------------------------------------------------
#define GTILE 16

__global__ __launch_bounds__(384, 2)
void dfine_proj_kernel(const float* __restrict__ hs,        // (BQ, 256)
                       const float* __restrict__ ref,       // (BQ, 4)
                       const float* __restrict__ W_off,     // (256, 256)
                       const float* __restrict__ b_off,     // (256,)
                       const float* __restrict__ W_attn,    // (256, 128)
                       const float* __restrict__ b_attn,    // (128,)
                       float* __restrict__ out_aw)          // d_out + NOUT0
{
    __shared__ float4 sh4[GTILE * 64];        // 16 rows x 256 floats
    const int bq0 = blockIdx.x * GTILE;
    const int tid = threadIdx.x;              // 0..383

    const float4* hs4 = (const float4*)hs + (size_t)bq0 * 64;
    for (int i = tid; i < GTILE * 64; i += 384)
        sh4[i] = hs4[i];
    __syncthreads();

    const bool is_off = (tid < 256);
    const float* Wp = is_off ? (W_off + tid) : (W_attn + (tid - 256));
    const int    ws = is_off ? 256 : 128;
    const float  bias = is_off ? b_off[tid] : b_attn[tid - 256];

    float acc[GTILE];
#pragma unroll
    for (int g = 0; g < GTILE; ++g) acc[g] = bias;

    // 8-deep prefetch pipeline on W column
    float w[8];
#pragma unroll
    for (int j = 0; j < 8; ++j) w[j] = __ldg(Wp + (size_t)j * ws);

#pragma unroll 1
    for (int k0 = 0; k0 < HIDDEN; k0 += 8) {
        float wn[8];
        const bool more = (k0 + 8) < HIDDEN;
#pragma unroll
        for (int j = 0; j < 8; ++j)
            wn[j] = more ? __ldg(Wp + (size_t)(k0 + 8 + j) * ws) : 0.0f;

        const int kb = k0 >> 2;
#pragma unroll
        for (int g = 0; g < GTILE; ++g) {
            const float4 A  = sh4[g * 64 + kb];
            const float4 Bv = sh4[g * 64 + kb + 1];
            float s = acc[g];
            s = fmaf(A.x,  w[0], s);
            s = fmaf(A.y,  w[1], s);
            s = fmaf(A.z,  w[2], s);
            s = fmaf(A.w,  w[3], s);
            s = fmaf(Bv.x, w[4], s);
            s = fmaf(Bv.y, w[5], s);
            s = fmaf(Bv.z, w[6], s);
            s = fmaf(Bv.w, w[7], s);
            acc[g] = s;
        }
#pragma unroll
        for (int j = 0; j < 8; ++j) w[j] = wn[j];
    }

    if (!is_off) {
        // softmax over the 16 points of each head (16-lane groups)
        const int idx = tid - 256;            // h*16 + p
#pragma unroll
        for (int g = 0; g < GTILE; ++g) {
            float v = acc[g];
            float m = v;
#pragma unroll
            for (int o = 8; o; o >>= 1)
                m = fmaxf(m, __shfl_xor_sync(0xffffffffu, m, o));
            float e = __expf(v - m);
            float s = e;
#pragma unroll
            for (int o = 8; o; o >>= 1)
                s += __shfl_xor_sync(0xffffffffu, s, o);
            out_aw[(size_t)(bq0 + g) * (NHEADS * PTOT) + idx] = e / s;
        }
    } else {
        // sampling locations: loc = ref_xy + acc * (1/4) * 0.5 * ref_wh
        const int c = tid & 1;
#pragma unroll
        for (int g = 0; g < GTILE; ++g) {
            const float4 r = __ldg((const float4*)ref + (bq0 + g));
            const float base = c ? r.y : r.x;
            const float wh   = c ? r.w : r.z;
            g_loc[(size_t)(bq0 + g) * 256 + tid] = fmaf(acc[g] * 0.125f, wh, base);
        }
    }
}

// ---------------------------------------------------------------------------
// Kernel B: bilinear sampling + weighted sum.
// Phase 1: 128 threads precompute per-(h,p) tap indices + folded weights.
// Phase 2: warp = head; lane = tap(4) x channel-quad(8); one LDG.128 per
//          (point, warp) covers all 4 taps x 32 channels. Cross-tap reduction
//          via 2 shuffle steps at the end.
// ---------------------------------------------------------------------------
__global__ __launch_bounds__(256)
void dfine_sample_kernel(const float* __restrict__ enc,     // (B, S, 256)
                         const float* __restrict__ aw,      // (BQ, 128)
                         float* __restrict__ out)           // (BQ, 256)
{
    __shared__ int   s_idx[128 * 4];
    __shared__ float s_w[128 * 4];

    const int bq  = blockIdx.x;
    const int b   = bq / NQ;
    const int tid = threadIdx.x;

    if (tid < 128) {
        const int hp = tid, hh = hp >> 4, p = hp & 15, lvl = p >> 2;
        const int w  = (lvl == 0) ? 100 : (lvl == 1) ? 50 : (lvl == 2) ? 25 : 13;
        const int st = (lvl == 0) ? 0 : (lvl == 1) ? 10000 : (lvl == 2) ? 12500 : 13125;
        // all levels are square: h == w

        const float lx = g_loc[(size_t)bq * 256 + hp * 2 + 0];
        const float ly = g_loc[(size_t)bq * 256 + hp * 2 + 1];
        const float a  = aw[(size_t)bq * 128 + hp];

        const float x = fmaf(lx, (float)w, -0.5f);
        const float y = fmaf(ly, (float)w, -0.5f);
        const float x0f = floorf(x), y0f = floorf(y);
        const int   x0 = (int)x0f,  y0 = (int)y0f;
        const float wx1 = x - x0f, wx0 = 1.0f - wx1;
        const float wy1 = y - y0f, wy0 = 1.0f - wy1;

        const bool vx0 = (x0 >= 0)  && (x0 < w);
        const bool vx1 = (x0 >= -1) && (x0 < w - 1);
        const bool vy0 = (y0 >= 0)  && (y0 < w);
        const bool vy1 = (y0 >= -1) && (y0 < w - 1);

        const int base = st * 256 + hh * 32;
        const int r0 = base + (y0 * w + x0) * 256;
        const int r1 = r0 + w * 256;

        s_idx[hp * 4 + 0] = (vy0 && vx0) ? r0       : -1;
        s_idx[hp * 4 + 1] = (vy0 && vx1) ? r0 + 256 : -1;
        s_idx[hp * 4 + 2] = (vy1 && vx0) ? r1       : -1;
        s_idx[hp * 4 + 3] = (vy1 && vx1) ? r1 + 256 : -1;
        s_w[hp * 4 + 0] = wy0 * wx0 * a;
        s_w[hp * 4 + 1] = wy0 * wx1 * a;
        s_w[hp * 4 + 2] = wy1 * wx0 * a;
        s_w[hp * 4 + 3] = wy1 * wx1 * a;
    }
    __syncthreads();

    const int h    = tid >> 5;
    const int lane = tid & 31;
    const int t    = lane >> 3;         // tap 0..3
    const int dq   = (lane & 7) << 2;   // channel quad start
    const float* encb = enc + (size_t)b * (SENC * 256) + dq;

    float ax = 0.f, ay = 0.f, az = 0.f, aq = 0.f;
#pragma unroll
    for (int p = 0; p < PTOT; ++p) {
        const int   idx = s_idx[(h * PTOT + p) * 4 + t];
        const float wt  = s_w[(h * PTOT + p) * 4 + t];
        if (idx >= 0) {
            const float4 v = __ldg((const float4*)(encb + idx));
            ax = fmaf(wt, v.x, ax);
            ay = fmaf(wt, v.y, ay);
            az = fmaf(wt, v.z, az);
            aq = fmaf(wt, v.w, aq);
        }
    }

    // sum across the 4 tap groups (lanes xor 8, xor 16)
#pragma unroll
    for (int o = 8; o <= 16; o <<= 1) {
        ax += __shfl_xor_sync(0xffffffffu, ax, o);
        ay += __shfl_xor_sync(0xffffffffu, ay, o);
        az += __shfl_xor_sync(0xffffffffu, az, o);
        aq += __shfl_xor_sync(0xffffffffu, aq, o);
    }

    if (lane < 8) {
        float4 r;
        r.x = ax; r.y = ay; r.z = az; r.w = aq;
        *(float4*)(out + (size_t)bq * 256 + h * 32 + dq) = r;
    }
}

// ---------------------------------------------------------------------------
extern "C" void kernel_launch(void* const* d_in, const int* in_sizes, int n_in,
                              void* d_out, int out_size)
{
    const float* hs     = (const float*)d_in[0];   // (B,Q,256)
    const float* enc    = (const float*)d_in[1];   // (B,S,256)
    const float* ref    = (const float*)d_in[2];   // (B,Q,1,4)
    const float* W_off  = (const float*)d_in[3];   // (256,256)
    const float* b_off  = (const float*)d_in[4];   // (256,)
    const float* W_attn = (const float*)d_in[5];   // (256,128)
    const float* b_attn = (const float*)d_in[6];   // (128,)

    float* out    = (float*)d_out;                 // (B,Q,256)
    float* out_aw = (float*)d_out + NOUT0;         // (B,Q,8,16)

    dfine_proj_kernel<<<NBQ / GTILE, 384>>>(hs, ref, W_off, b_off, W_attn,
                                            b_attn, out_aw);
    dfine_sample_kernel<<<NBQ, 256>>>(enc, out_aw, out);
}

// round 4
// speedup vs baseline: 2.0719x; 1.0133x over previous
#include <cuda_runtime.h>
#include <cstdint>

// ---------------------------------------------------------------------------
// DFine Multiscale Deformable Attention
//   B=16, Q=300, HIDDEN=256, N_HEADS=8, d=32
//   SPATIAL = (100,100),(50,50),(25,25),(13,13)  -> S=13294
//   NUM_POINTS = 4 per level -> p_total=16, total_points = 128
// Output = concat( out[B,Q,256], aw[B,Q,8,16] )  (float32)
// ---------------------------------------------------------------------------

#define NB        16
#define NQ        300
#define NBQ       (NB * NQ)          // 4800
#define HIDDEN    256
#define NHEADS    8
#define PTOT      16
#define NOUT0     (NBQ * HIDDEN)
#define SENC      13294

typedef unsigned long long ull;

// per-(b,q): 8 heads * 16 points * 2 coords
__device__ float g_loc[NBQ * NHEADS * PTOT * 2];

__device__ __forceinline__ ull pk2(float lo, float hi) {
    ull r; asm("mov.b64 %0, {%1,%2};" : "=l"(r) : "f"(lo), "f"(hi)); return r;
}
__device__ __forceinline__ void upk2(float& lo, float& hi, ull v) {
    asm("mov.b64 {%0,%1}, %2;" : "=f"(lo), "=f"(hi) : "l"(v));
}
#define FFMA2(d, a, b) asm("fma.rn.f32x2 %0, %1, %2, %0;" : "+l"(d) : "l"(a), "l"(b))

// ---------------------------------------------------------------------------
// Kernel A: projection GEMM (offsets + attn logits) + softmax + sampling locs.
// 384 threads = one output column each (256 offset + 128 attn), GTILE=16 rows.
// f32x2 packed FMA: shared holds row-PAIRS pre-packed as u64, so each
// ld.shared.v2.b64 yields two ready multiplicand pairs. 8-deep W prefetch.
// ---------------------------------------------------------------------------
#define GTILE 16

__global__ __launch_bounds__(384, 2)
void dfine_proj_kernel(const float* __restrict__ hs,        // (BQ, 256)
                       const float* __restrict__ ref,       // (BQ, 4)
                       const float* __restrict__ W_off,     // (256, 256)
                       const float* __restrict__ b_off,     // (256,)
                       const float* __restrict__ W_attn,    // (256, 128)
                       const float* __restrict__ b_attn,    // (128,)
                       float* __restrict__ out_aw)          // d_out + NOUT0
{
    __shared__ ull shP[8 * 256];              // [gp][k]: pack(hs[2gp][k], hs[2gp+1][k])
    const int bq0 = blockIdx.x * GTILE;
    const int tid = threadIdx.x;              // 0..383

    const float* hsb = hs + (size_t)bq0 * HIDDEN;
    for (int i = tid; i < 8 * 256; i += 384) {
        const int gp = i >> 8, k = i & 255;
        const float a = hsb[(2 * gp)     * 256 + k];
        const float b = hsb[(2 * gp + 1) * 256 + k];
        shP[gp * 256 + k] = pk2(a, b);
    }
    __syncthreads();

    const bool is_off = (tid < 256);
    const float* Wp = is_off ? (W_off + tid) : (W_attn + (tid - 256));
    const int    ws = is_off ? 256 : 128;
    const float  bias = is_off ? b_off[tid] : b_attn[tid - 256];

    ull acc2[8];
#pragma unroll
    for (int gp = 0; gp < 8; ++gp) acc2[gp] = pk2(bias, bias);

    float w[8];
#pragma unroll
    for (int j = 0; j < 8; ++j) w[j] = __ldg(Wp + (size_t)j * ws);

#pragma unroll 1
    for (int k0 = 0; k0 < HIDDEN; k0 += 8) {
        float wn[8];
        const bool more = (k0 + 8) < HIDDEN;
#pragma unroll
        for (int j = 0; j < 8; ++j)
            wn[j] = more ? __ldg(Wp + (size_t)(k0 + 8 + j) * ws) : 0.0f;

        ull wd[8];
#pragma unroll
        for (int j = 0; j < 8; ++j) wd[j] = pk2(w[j], w[j]);

#pragma unroll
        for (int gp = 0; gp < 8; ++gp) {
            const ull* row = shP + gp * 256 + k0;
#pragma unroll
            for (int jj = 0; jj < 4; ++jj) {
                const ulonglong2 p = *(const ulonglong2*)(row + 2 * jj);
                FFMA2(acc2[gp], p.x, wd[2 * jj]);
                FFMA2(acc2[gp], p.y, wd[2 * jj + 1]);
            }
        }
#pragma unroll
        for (int j = 0; j < 8; ++j) w[j] = wn[j];
    }

    float acc[GTILE];
#pragma unroll
    for (int gp = 0; gp < 8; ++gp)
        upk2(acc[2 * gp], acc[2 * gp + 1], acc2[gp]);

    if (!is_off) {
        // softmax over the 16 points of each head (16-lane groups)
        const int idx = tid - 256;            // h*16 + p
#pragma unroll
        for (int g = 0; g < GTILE; ++g) {
            float v = acc[g];
            float m = v;
#pragma unroll
            for (int o = 8; o; o >>= 1)
                m = fmaxf(m, __shfl_xor_sync(0xffffffffu, m, o));
            float e = __expf(v - m);
            float s = e;
#pragma unroll
            for (int o = 8; o; o >>= 1)
                s += __shfl_xor_sync(0xffffffffu, s, o);
            out_aw[(size_t)(bq0 + g) * (NHEADS * PTOT) + idx] = e / s;
        }
    } else {
        // sampling locations: loc = ref_xy + acc * (1/4) * 0.5 * ref_wh
        const int c = tid & 1;
#pragma unroll
        for (int g = 0; g < GTILE; ++g) {
            const float4 r = __ldg((const float4*)ref + (bq0 + g));
            const float base = c ? r.y : r.x;
            const float wh   = c ? r.w : r.z;
            g_loc[(size_t)(bq0 + g) * 256 + tid] = fmaf(acc[g] * 0.125f, wh, base);
        }
    }
}

// ---------------------------------------------------------------------------
// Kernel B: bilinear sampling + weighted sum.
// Phase 1: 128 threads precompute per-(h,p,tap) {offset, folded weight};
//          invalid taps become {0, 0.0f} (branch-free).
// Phase 2: warp = head; lane = tap(4) x channel-quad(8). Loads are
//          front-batched 8-deep for MLP. Cross-tap reduction via shuffles.
// ---------------------------------------------------------------------------
__global__ __launch_bounds__(256)
void dfine_sample_kernel(const float* __restrict__ enc,     // (B, S, 256)
                         const float* __restrict__ aw,      // (BQ, 128)
                         float* __restrict__ out)           // (BQ, 256)
{
    __shared__ int2 s_tap[128 * 4];           // (byte/float offset, weight bits)

    const int bq  = blockIdx.x;
    const int b   = bq / NQ;
    const int tid = threadIdx.x;

    if (tid < 128) {
        const int hp = tid, hh = hp >> 4, p = hp & 15, lvl = p >> 2;
        const int w  = (lvl == 0) ? 100 : (lvl == 1) ? 50 : (lvl == 2) ? 25 : 13;
        const int st = (lvl == 0) ? 0 : (lvl == 1) ? 10000 : (lvl == 2) ? 12500 : 13125;

        const float lx = g_loc[(size_t)bq * 256 + hp * 2 + 0];
        const float ly = g_loc[(size_t)bq * 256 + hp * 2 + 1];
        const float a  = aw[(size_t)bq * 128 + hp];

        const float x = fmaf(lx, (float)w, -0.5f);
        const float y = fmaf(ly, (float)w, -0.5f);
        const float x0f = floorf(x), y0f = floorf(y);
        const int   x0 = (int)x0f,  y0 = (int)y0f;
        const float wx1 = x - x0f, wx0 = 1.0f - wx1;
        const float wy1 = y - y0f, wy0 = 1.0f - wy1;

        const bool vx0 = (x0 >= 0)  && (x0 < w);
        const bool vx1 = (x0 >= -1) && (x0 < w - 1);
        const bool vy0 = (y0 >= 0)  && (y0 < w);
        const bool vy1 = (y0 >= -1) && (y0 < w - 1);

        const int base = st * 256 + hh * 32;
        const int r0 = base + (y0 * w + x0) * 256;
        const int r1 = r0 + w * 256;

        const bool v00 = vy0 && vx0, v01 = vy0 && vx1;
        const bool v10 = vy1 && vx0, v11 = vy1 && vx1;
        s_tap[hp * 4 + 0] = make_int2(v00 ? r0       : 0, __float_as_int(v00 ? wy0 * wx0 * a : 0.f));
        s_tap[hp * 4 + 1] = make_int2(v01 ? r0 + 256 : 0, __float_as_int(v01 ? wy0 * wx1 * a : 0.f));
        s_tap[hp * 4 + 2] = make_int2(v10 ? r1       : 0, __float_as_int(v10 ? wy1 * wx0 * a : 0.f));
        s_tap[hp * 4 + 3] = make_int2(v11 ? r1 + 256 : 0, __float_as_int(v11 ? wy1 * wx1 * a : 0.f));
    }
    __syncthreads();

    const int h    = tid >> 5;
    const int lane = tid & 31;
    const int t    = lane >> 3;         // tap 0..3
    const int dq   = (lane & 7) << 2;   // channel quad start
    const float* encb = enc + (size_t)b * (SENC * 256) + dq;

    float ax = 0.f, ay = 0.f, az = 0.f, aq = 0.f;

#pragma unroll
    for (int pb = 0; pb < PTOT; pb += 8) {
        int   idx[8];
        float wt[8];
#pragma unroll
        for (int j = 0; j < 8; ++j) {
            const int2 tp = s_tap[(h * PTOT + pb + j) * 4 + t];
            idx[j] = tp.x;
            wt[j]  = __int_as_float(tp.y);
        }
        float4 v[8];
#pragma unroll
        for (int j = 0; j < 8; ++j)
            v[j] = __ldg((const float4*)(encb + idx[j]));
#pragma unroll
        for (int j = 0; j < 8; ++j) {
            ax = fmaf(wt[j], v[j].x, ax);
            ay = fmaf(wt[j], v[j].y, ay);
            az = fmaf(wt[j], v[j].z, az);
            aq = fmaf(wt[j], v[j].w, aq);
        }
    }

    // sum across the 4 tap groups (lanes xor 8, xor 16)
#pragma unroll
    for (int o = 8; o <= 16; o <<= 1) {
        ax += __shfl_xor_sync(0xffffffffu, ax, o);
        ay += __shfl_xor_sync(0xffffffffu, ay, o);
        az += __shfl_xor_sync(0xffffffffu, az, o);
        aq += __shfl_xor_sync(0xffffffffu, aq, o);
    }

    if (lane < 8) {
        float4 r;
        r.x = ax; r.y = ay; r.z = az; r.w = aq;
        *(float4*)(out + (size_t)bq * 256 + h * 32 + dq) = r;
    }
}

// ---------------------------------------------------------------------------
extern "C" void kernel_launch(void* const* d_in, const int* in_sizes, int n_in,
                              void* d_out, int out_size)
{
    const float* hs     = (const float*)d_in[0];   // (B,Q,256)
    const float* enc    = (const float*)d_in[1];   // (B,S,256)
    const float* ref    = (const float*)d_in[2];   // (B,Q,1,4)
    const float* W_off  = (const float*)d_in[3];   // (256,256)
    const float* b_off  = (const float*)d_in[4];   // (256,)
    const float* W_attn = (const float*)d_in[5];   // (256,128)
    const float* b_attn = (const float*)d_in[6];   // (128,)

    float* out    = (float*)d_out;                 // (B,Q,256)
    float* out_aw = (float*)d_out + NOUT0;         // (B,Q,8,16)

    dfine_proj_kernel<<<NBQ / GTILE, 384>>>(hs, ref, W_off, b_off, W_attn,
                                            b_attn, out_aw);
    dfine_sample_kernel<<<NBQ, 256>>>(enc, out_aw, out);
}